// round 14
// baseline (speedup 1.0000x reference)
#include <cuda_runtime.h>
#include <cuda_fp16.h>

#define NN 100000
#define NE 3200000
#define F1 16
#define CAP 64                       // slots per node (Poisson(32): P(>64)~4e-6/node; spill path handles rest)
#define OVF_MAX (1 << 20)

#define GEMM_BLKS 196                // 196 * 512 nodes
#define FILL_BLKS (NE / 4 / 256)     // 3125 (4 edges per thread)

// ---- static device scratch (no cudaMalloc allowed) ----
__device__ float  g_h0f[NN * F1];    // (x @ W1) [* dinv after k_scale], fp32
__device__ float  g_gs[NN];          // layer-1 output * dinv[node]
__device__ float  g_dinv[NN];
__device__ int    g_csr[NN * CAP];   // padded bins: src, grouped by dst
__device__ struct {
    int cursor[NN];
    int ovf_cnt;
    int2 ovf[OVF_MAX];               // NOT memset (only first ovf_cnt valid)
} g_dyn;                             // prefix zeroed each launch with ONE memset

// ---- f32x2 helpers (Blackwell packed fp32) ----
__device__ __forceinline__ unsigned long long pack64(unsigned a, unsigned b) {
    unsigned long long r;
    asm("mov.b64 %0, {%1,%2};" : "=l"(r) : "r"(a), "r"(b));
    return r;
}
__device__ __forceinline__ void unpack64(unsigned long long v, float& a, float& b) {
    unsigned x, y;
    asm("mov.b64 {%0,%1}, %2;" : "=r"(x), "=r"(y) : "l"(v));
    a = __uint_as_float(x);
    b = __uint_as_float(y);
}
__device__ __forceinline__ void addx2(unsigned long long& acc, unsigned long long v) {
    asm("add.rn.f32x2 %0, %0, %1;" : "+l"(acc) : "l"(v));
}
__device__ __forceinline__ unsigned long long shfl_xor64(unsigned long long v, int off) {
    unsigned x, y;
    asm("mov.b64 {%0,%1}, %2;" : "=r"(x), "=r"(y) : "l"(v));
    x = __shfl_xor_sync(0xffffffffu, x, off);
    y = __shfl_xor_sync(0xffffffffu, y, off);
    return pack64(x, y);
}

// ---------------- fused: GEMM1 + CSR bin-fill (independent work) -----------
__global__ __launch_bounds__(256) void k_fill_gemm(
    const float* __restrict__ x, const float* __restrict__ W1,
    const void* __restrict__ ei) {
    if (blockIdx.x >= GEMM_BLKS) {
        // ---- inline dtype detect (parallel, L2-hot) ----
        int bad = 0;
        if (threadIdx.x < 64)
            bad = (__ldg((const unsigned int*)ei + 2 * threadIdx.x + 1) != 0u);
        int is64 = !__syncthreads_or(bad);

        // ---- fill: 4 edges/thread ----
        int base = ((blockIdx.x - GEMM_BLKS) * 256 + threadIdx.x) * 4;
        int r[4], c[4];
        if (is64) {
            const int4* p = (const int4*)ei;            // row half
            const int4* q = (const int4*)ei + NE / 2;   // col half
            int4 a = __ldg(p + base / 2);
            int4 b = __ldg(p + base / 2 + 1);
            int4 d = __ldg(q + base / 2);
            int4 e = __ldg(q + base / 2 + 1);
            r[0] = a.x; r[1] = a.z; r[2] = b.x; r[3] = b.z;
            c[0] = d.x; c[1] = d.z; c[2] = e.x; c[3] = e.z;
        } else {
            int4 a = __ldg((const int4*)((const int*)ei) + base / 4);
            int4 d = __ldg((const int4*)((const int*)ei + NE) + base / 4);
            r[0] = a.x; r[1] = a.y; r[2] = a.z; r[3] = a.w;
            c[0] = d.x; c[1] = d.y; c[2] = d.z; c[3] = d.w;
        }
        int s[4];
        #pragma unroll
        for (int j = 0; j < 4; j++) s[j] = atomicAdd(&g_dyn.cursor[c[j]], 1);
        #pragma unroll
        for (int j = 0; j < 4; j++) {
            if (s[j] < CAP) {
                g_csr[(c[j] << 6) + s[j]] = r[j];
            } else {                      // guaranteed-correct spill path
                int o = atomicAdd(&g_dyn.ovf_cnt, 1);
                if (o < OVF_MAX) g_dyn.ovf[o] = make_int2(r[j], c[j]);
            }
        }
        return;
    }
    // ---- GEMM: h0f = x @ W1, fp32, unscaled ----
    __shared__ float ws[128 * F1];
    for (int t = threadIdx.x; t < 128 * F1; t += 256) ws[t] = W1[t];
    __syncthreads();

    int nbase = blockIdx.x * 512 + threadIdx.x;
    float acc[2][F1];
    #pragma unroll
    for (int nn = 0; nn < 2; nn++)
        #pragma unroll
        for (int j = 0; j < F1; j++) acc[nn][j] = 0.0f;

    #pragma unroll 4
    for (int k4 = 0; k4 < 32; k4++) {
        float4 xr[2];
        #pragma unroll
        for (int nn = 0; nn < 2; nn++) {
            int node = nbase + nn * 256;
            xr[nn] = (node < NN)
                ? __ldg((const float4*)(x + (long long)node * 128) + k4)
                : make_float4(0.f, 0.f, 0.f, 0.f);
        }
        #pragma unroll
        for (int kk = 0; kk < 4; kk++) {
            #pragma unroll
            for (int j = 0; j < F1; j++) {
                float wv = ws[(k4 * 4 + kk) * F1 + j];
                #pragma unroll
                for (int nn = 0; nn < 2; nn++) {
                    const float* xa = (const float*)&xr[nn];
                    acc[nn][j] = fmaf(xa[kk], wv, acc[nn][j]);
                }
            }
        }
    }
    #pragma unroll
    for (int nn = 0; nn < 2; nn++) {
        int node = nbase + nn * 256;
        if (node < NN) {
            float4* o = (float4*)(g_h0f + (long long)node * F1);
            o[0] = make_float4(acc[nn][0], acc[nn][1], acc[nn][2], acc[nn][3]);
            o[1] = make_float4(acc[nn][4], acc[nn][5], acc[nn][6], acc[nn][7]);
            o[2] = make_float4(acc[nn][8], acc[nn][9], acc[nn][10], acc[nn][11]);
            o[3] = make_float4(acc[nn][12], acc[nn][13], acc[nn][14], acc[nn][15]);
        }
    }
}

// ---------------- scale: dinv from cursor counts; h0f *= dinv --------------
__global__ __launch_bounds__(256) void k_scale() {
    int i = blockIdx.x * 256 + threadIdx.x;
    if (i >= NN) return;
    int cnt = g_dyn.cursor[i];
    float di = rsqrtf((float)cnt + 1.0f);
    g_dinv[i] = di;
    float4* row = (float4*)(g_h0f + (long long)i * F1);
    #pragma unroll
    for (int j = 0; j < 4; j++) {
        float4 v = row[j];
        row[j] = make_float4(v.x * di, v.y * di, v.z * di, v.w * di);
    }
}

// ---------------- gather1: preloaded bin, 8 unrolled gathers, f32x2 --------
// q = lane>>2 selects edge slot group, f4 = lane&3 selects 16B quarter
__global__ __launch_bounds__(256) void k_gather1(
    const float* __restrict__ b1, const float* __restrict__ W2) {
    int node = (blockIdx.x * blockDim.x + threadIdx.x) >> 5;
    int lane = threadIdx.x & 31;
    if (node >= NN) return;
    int cnt = g_dyn.cursor[node];
    int len = min(cnt, CAP);
    const int* bin = g_csr + (node << 6);
    int q  = lane >> 2;
    int f4 = lane & 3;

    // preload whole bin cooperatively (2 coalesced 128B loads)
    int sv0 = __ldg(bin + lane);        // slots [0,32)
    int sv1 = __ldg(bin + lane + 32);   // slots [32,64)

    // self-loop (h0f already dinv-scaled) on edge-slot group 0
    unsigned long long a01 = 0ull, a23 = 0ull;
    if (q == 0) {
        uint4 s = __ldg((const uint4*)(g_h0f + (long long)node * F1) + f4);
        a01 = pack64(s.x, s.y);
        a23 = pack64(s.z, s.w);
    }

    // 8 independent predicated gathers (edges q, q+8, ..., q+56)
    uint4 v[8];
    #pragma unroll
    for (int t = 0; t < 8; t++) {
        int e = q + 8 * t;
        int src = (t < 4) ? __shfl_sync(0xffffffffu, sv0, e)
                          : __shfl_sync(0xffffffffu, sv1, e - 32);
        v[t] = make_uint4(0u, 0u, 0u, 0u);
        if (e < len)
            v[t] = __ldg((const uint4*)(g_h0f + (long long)src * F1) + f4);
    }
    #pragma unroll
    for (int t = 0; t < 8; t++) {
        addx2(a01, pack64(v[t].x, v[t].y));
        addx2(a23, pack64(v[t].z, v[t].w));
    }

    // reduce across the 8 edge-slot groups (keep f4 split): packed adds
    #pragma unroll
    for (int off = 4; off < 32; off <<= 1) {
        addx2(a01, shfl_xor64(a01, off));
        addx2(a23, shfl_xor64(a23, off));
    }
    float di = __ldg(&g_dinv[node]);
    float vv = 0.0f;
    if (lane < 4) {
        float ax, ay, az, aw;
        unpack64(a01, ax, ay);
        unpack64(a23, az, aw);
        if (cnt > CAP) {    // overflow path (correct; ~never taken)
            int no = min(g_dyn.ovf_cnt, OVF_MAX);
            for (int o = 0; o < no; o++) {
                int2 rc = g_dyn.ovf[o];
                if (rc.y == node) {
                    float4 u = __ldg((const float4*)(g_h0f + (long long)rc.x * F1) + f4);
                    ax += u.x; ay += u.y; az += u.z; aw += u.w;
                }
            }
        }
        float4 bb = __ldg((const float4*)b1 + lane);
        float4 ww = __ldg((const float4*)W2 + lane);
        float t0 = fmaxf(fmaf(ax, di, bb.x), 0.f) * ww.x;
        float t1 = fmaxf(fmaf(ay, di, bb.y), 0.f) * ww.y;
        float t2 = fmaxf(fmaf(az, di, bb.z), 0.f) * ww.z;
        float t3 = fmaxf(fmaf(aw, di, bb.w), 0.f) * ww.w;
        vv = (t0 + t1) + (t2 + t3);
    }
    vv += __shfl_xor_sync(0xffffffffu, vv, 1);
    vv += __shfl_xor_sync(0xffffffffu, vv, 2);
    if (lane == 0) g_gs[node] = vv * di;
}

// ---------------- gather2: 4 nodes/warp, 8 lanes/node -----------------------
__global__ __launch_bounds__(256) void k_gather2(
    const float* __restrict__ b2, float* __restrict__ out) {
    int w = (blockIdx.x * blockDim.x + threadIdx.x) >> 5;
    int lane = threadIdx.x & 31;
    int sub = lane >> 3;             // which node in this warp (0..3)
    int hl  = lane & 7;              // lane within 8-lane group
    int node = w * 4 + sub;
    if (node >= NN) return;
    int cnt = g_dyn.cursor[node];
    int len = min(cnt, CAP);
    const int* bin = g_csr + (node << 6);

    // 4 (or 8) independent csr+gather chains per lane
    int s0 = __ldg(bin + hl);
    int s1 = __ldg(bin + hl + 8);
    int s2 = __ldg(bin + hl + 16);
    int s3 = __ldg(bin + hl + 24);
    float acc = 0.0f;
    if (hl < len)      acc += __ldg(&g_gs[s0]);
    if (hl + 8 < len)  acc += __ldg(&g_gs[s1]);
    if (hl + 16 < len) acc += __ldg(&g_gs[s2]);
    if (hl + 24 < len) acc += __ldg(&g_gs[s3]);
    if (len > 32) {
        int s4 = __ldg(bin + hl + 32);
        int s5 = __ldg(bin + hl + 40);
        int s6 = __ldg(bin + hl + 48);
        int s7 = __ldg(bin + hl + 56);
        if (hl + 32 < len) acc += __ldg(&g_gs[s4]);
        if (hl + 40 < len) acc += __ldg(&g_gs[s5]);
        if (hl + 48 < len) acc += __ldg(&g_gs[s6]);
        if (hl + 56 < len) acc += __ldg(&g_gs[s7]);
    }
    if (hl == 0) {
        acc += __ldg(&g_gs[node]);   // self loop
        if (cnt > CAP) {             // overflow path (correct; ~never taken)
            int no = min(g_dyn.ovf_cnt, OVF_MAX);
            for (int o = 0; o < no; o++) {
                int2 rc = g_dyn.ovf[o];
                if (rc.y == node) acc += __ldg(&g_gs[rc.x]);
            }
        }
    }

    // reduce within the 8-lane group
    acc += __shfl_xor_sync(0xffffffffu, acc, 4);
    acc += __shfl_xor_sync(0xffffffffu, acc, 2);
    acc += __shfl_xor_sync(0xffffffffu, acc, 1);
    if (hl == 0) {
        float v = fmaf(acc, __ldg(&g_dinv[node]), __ldg(&b2[0]));
        out[node] = 1.0f / (1.0f + __expf(-v));
    }
}

// ---------------- launch ----------------------------------------------------
extern "C" void kernel_launch(void* const* d_in, const int* in_sizes, int n_in,
                              void* d_out, int out_size) {
    const float* x  = (const float*)d_in[0];
    const void*  ei = d_in[1];
    const float* W1 = (const float*)d_in[2];
    const float* b1 = (const float*)d_in[3];
    const float* W2 = (const float*)d_in[4];
    const float* b2 = (const float*)d_in[5];
    float* out = (float*)d_out;

    static void* dyn_addr = nullptr;
    if (!dyn_addr) cudaGetSymbolAddress(&dyn_addr, g_dyn);

    // zero cursors + ovf_cnt only (prefix of g_dyn)
    cudaMemsetAsync(dyn_addr, 0, (size_t)(NN + 1) * sizeof(int));
    k_fill_gemm<<<GEMM_BLKS + FILL_BLKS, 256>>>(x, W1, ei);
    k_scale<<<(NN + 255) / 256, 256>>>();
    k_gather1<<<(NN * 32 + 255) / 256, 256>>>(b1, W2);
    k_gather2<<<(NN * 8 + 255) / 256, 256>>>(b2, out);
}

// round 15
// speedup vs baseline: 1.0305x; 1.0305x over previous
#include <cuda_runtime.h>
#include <cuda_fp16.h>

#define NN 100000
#define NE 3200000
#define F1 16
#define CAP 64                       // slots per node (Poisson(32): P(>64)~4e-6/node; spill path handles rest)
#define OVF_MAX (1 << 20)

#define GEMM_BLKS 196                // 196 * 512 nodes
#define FILL_BLKS (NE / 4 / 256)     // 3125 (4 edges per thread)

// ---- static device scratch (no cudaMalloc allowed) ----
__device__ float  g_h0f[NN * F1];    // (x @ W1) [* dinv after k_scale], fp32
__device__ float  g_gs[NN];          // layer-1 output * dinv[node]
__device__ float  g_dinv[NN];
__device__ int    g_csr[NN * CAP];   // padded bins: src, grouped by dst
__device__ struct {
    int cursor[NN];
    int ovf_cnt;
    int2 ovf[OVF_MAX];               // NOT memset (only first ovf_cnt valid)
} g_dyn;                             // prefix zeroed each launch with ONE memset

// ---- f32x2 helpers (Blackwell packed fp32) ----
__device__ __forceinline__ unsigned long long pack64(unsigned a, unsigned b) {
    unsigned long long r;
    asm("mov.b64 %0, {%1,%2};" : "=l"(r) : "r"(a), "r"(b));
    return r;
}
__device__ __forceinline__ void unpack64(unsigned long long v, float& a, float& b) {
    unsigned x, y;
    asm("mov.b64 {%0,%1}, %2;" : "=r"(x), "=r"(y) : "l"(v));
    a = __uint_as_float(x);
    b = __uint_as_float(y);
}
__device__ __forceinline__ void addx2(unsigned long long& acc, unsigned long long v) {
    asm("add.rn.f32x2 %0, %0, %1;" : "+l"(acc) : "l"(v));
}
__device__ __forceinline__ unsigned long long shfl_xor64(unsigned long long v, int off) {
    unsigned x, y;
    asm("mov.b64 {%0,%1}, %2;" : "=r"(x), "=r"(y) : "l"(v));
    x = __shfl_xor_sync(0xffffffffu, x, off);
    y = __shfl_xor_sync(0xffffffffu, y, off);
    return pack64(x, y);
}

// ---------------- fused: GEMM1 + CSR bin-fill (independent work) -----------
__global__ __launch_bounds__(256) void k_fill_gemm(
    const float* __restrict__ x, const float* __restrict__ W1,
    const void* __restrict__ ei) {
    if (blockIdx.x >= GEMM_BLKS) {
        // ---- inline dtype detect (parallel, L2-hot) ----
        int bad = 0;
        if (threadIdx.x < 64)
            bad = (__ldg((const unsigned int*)ei + 2 * threadIdx.x + 1) != 0u);
        int is64 = !__syncthreads_or(bad);

        // ---- fill: 4 edges/thread ----
        int base = ((blockIdx.x - GEMM_BLKS) * 256 + threadIdx.x) * 4;
        int r[4], c[4];
        if (is64) {
            const int4* p = (const int4*)ei;            // row half
            const int4* q = (const int4*)ei + NE / 2;   // col half
            int4 a = __ldg(p + base / 2);
            int4 b = __ldg(p + base / 2 + 1);
            int4 d = __ldg(q + base / 2);
            int4 e = __ldg(q + base / 2 + 1);
            r[0] = a.x; r[1] = a.z; r[2] = b.x; r[3] = b.z;
            c[0] = d.x; c[1] = d.z; c[2] = e.x; c[3] = e.z;
        } else {
            int4 a = __ldg((const int4*)((const int*)ei) + base / 4);
            int4 d = __ldg((const int4*)((const int*)ei + NE) + base / 4);
            r[0] = a.x; r[1] = a.y; r[2] = a.z; r[3] = a.w;
            c[0] = d.x; c[1] = d.y; c[2] = d.z; c[3] = d.w;
        }
        int s[4];
        #pragma unroll
        for (int j = 0; j < 4; j++) s[j] = atomicAdd(&g_dyn.cursor[c[j]], 1);
        #pragma unroll
        for (int j = 0; j < 4; j++) {
            if (s[j] < CAP) {
                g_csr[(c[j] << 6) + s[j]] = r[j];
            } else {                      // guaranteed-correct spill path
                int o = atomicAdd(&g_dyn.ovf_cnt, 1);
                if (o < OVF_MAX) g_dyn.ovf[o] = make_int2(r[j], c[j]);
            }
        }
        return;
    }
    // ---- GEMM: h0f = x @ W1, fp32, unscaled ----
    __shared__ float ws[128 * F1];
    for (int t = threadIdx.x; t < 128 * F1; t += 256) ws[t] = W1[t];
    __syncthreads();

    int nbase = blockIdx.x * 512 + threadIdx.x;
    float acc[2][F1];
    #pragma unroll
    for (int nn = 0; nn < 2; nn++)
        #pragma unroll
        for (int j = 0; j < F1; j++) acc[nn][j] = 0.0f;

    #pragma unroll 4
    for (int k4 = 0; k4 < 32; k4++) {
        float4 xr[2];
        #pragma unroll
        for (int nn = 0; nn < 2; nn++) {
            int node = nbase + nn * 256;
            xr[nn] = (node < NN)
                ? __ldg((const float4*)(x + (long long)node * 128) + k4)
                : make_float4(0.f, 0.f, 0.f, 0.f);
        }
        #pragma unroll
        for (int kk = 0; kk < 4; kk++) {
            #pragma unroll
            for (int j = 0; j < F1; j++) {
                float wv = ws[(k4 * 4 + kk) * F1 + j];
                #pragma unroll
                for (int nn = 0; nn < 2; nn++) {
                    const float* xa = (const float*)&xr[nn];
                    acc[nn][j] = fmaf(xa[kk], wv, acc[nn][j]);
                }
            }
        }
    }
    #pragma unroll
    for (int nn = 0; nn < 2; nn++) {
        int node = nbase + nn * 256;
        if (node < NN) {
            float4* o = (float4*)(g_h0f + (long long)node * F1);
            o[0] = make_float4(acc[nn][0], acc[nn][1], acc[nn][2], acc[nn][3]);
            o[1] = make_float4(acc[nn][4], acc[nn][5], acc[nn][6], acc[nn][7]);
            o[2] = make_float4(acc[nn][8], acc[nn][9], acc[nn][10], acc[nn][11]);
            o[3] = make_float4(acc[nn][12], acc[nn][13], acc[nn][14], acc[nn][15]);
        }
    }
}

// ---------------- scale: dinv from cursor counts; h0f *= dinv --------------
__global__ __launch_bounds__(256) void k_scale() {
    int i = blockIdx.x * 256 + threadIdx.x;
    if (i >= NN) return;
    int cnt = g_dyn.cursor[i];
    float di = rsqrtf((float)cnt + 1.0f);
    g_dinv[i] = di;
    float4* row = (float4*)(g_h0f + (long long)i * F1);
    #pragma unroll
    for (int j = 0; j < 4; j++) {
        float4 v = row[j];
        row[j] = make_float4(v.x * di, v.y * di, v.z * di, v.w * di);
    }
}

// ---------------- gather1: warp/node, 8-edge loop, f32x2 accumulate --------
// q = lane>>2 selects edge slot (8 per iter), f4 = lane&3 selects 16B quarter
__global__ __launch_bounds__(256) void k_gather1(
    const float* __restrict__ b1, const float* __restrict__ W2) {
    int node = (blockIdx.x * blockDim.x + threadIdx.x) >> 5;
    int lane = threadIdx.x & 31;
    if (node >= NN) return;
    int cnt = g_dyn.cursor[node];
    int len = min(cnt, CAP);
    const int* bin = g_csr + (node << 6);
    int q  = lane >> 2;
    int f4 = lane & 3;

    // packed accumulators: a01 = features (0,1) of the quarter, a23 = (2,3)
    unsigned long long a01 = 0ull, a23 = 0ull;
    if (q == 0) {
        uint4 s = __ldg((const uint4*)(g_h0f + (long long)node * F1) + f4);
        a01 = pack64(s.x, s.y);
        a23 = pack64(s.z, s.w);
    }

    for (int p = 0; p < len; p += 8) {
        int idx = p + q;
        if (idx < len) {
            int src = __ldg(bin + idx);
            uint4 v = __ldg((const uint4*)(g_h0f + (long long)src * F1) + f4);
            addx2(a01, pack64(v.x, v.y));
            addx2(a23, pack64(v.z, v.w));
        }
    }
    // reduce across the 8 edge-slots (keep f4 split): packed adds
    #pragma unroll
    for (int off = 4; off < 32; off <<= 1) {
        addx2(a01, shfl_xor64(a01, off));
        addx2(a23, shfl_xor64(a23, off));
    }
    float di = __ldg(&g_dinv[node]);
    float v = 0.0f;
    if (lane < 4) {
        float ax, ay, az, aw;
        unpack64(a01, ax, ay);
        unpack64(a23, az, aw);
        if (cnt > CAP) {    // overflow path (correct; ~never taken)
            int no = min(g_dyn.ovf_cnt, OVF_MAX);
            for (int o = 0; o < no; o++) {
                int2 rc = g_dyn.ovf[o];
                if (rc.y == node) {
                    float4 u = __ldg((const float4*)(g_h0f + (long long)rc.x * F1) + f4);
                    ax += u.x; ay += u.y; az += u.z; aw += u.w;
                }
            }
        }
        float4 bb = __ldg((const float4*)b1 + lane);
        float4 ww = __ldg((const float4*)W2 + lane);
        float t0 = fmaxf(fmaf(ax, di, bb.x), 0.f) * ww.x;
        float t1 = fmaxf(fmaf(ay, di, bb.y), 0.f) * ww.y;
        float t2 = fmaxf(fmaf(az, di, bb.z), 0.f) * ww.z;
        float t3 = fmaxf(fmaf(aw, di, bb.w), 0.f) * ww.w;
        v = (t0 + t1) + (t2 + t3);
    }
    v += __shfl_xor_sync(0xffffffffu, v, 1);
    v += __shfl_xor_sync(0xffffffffu, v, 2);
    if (lane == 0) g_gs[node] = v * di;
}

// ---------------- gather2: 4 nodes/warp, 8 lanes/node -----------------------
__global__ __launch_bounds__(256) void k_gather2(
    const float* __restrict__ b2, float* __restrict__ out) {
    int w = (blockIdx.x * blockDim.x + threadIdx.x) >> 5;
    int lane = threadIdx.x & 31;
    int sub = lane >> 3;             // which node in this warp (0..3)
    int hl  = lane & 7;              // lane within 8-lane group
    int node = w * 4 + sub;
    if (node >= NN) return;
    int cnt = g_dyn.cursor[node];
    int len = min(cnt, CAP);
    const int* bin = g_csr + (node << 6);

    // 4 (or 8) independent csr+gather chains per lane
    int s0 = __ldg(bin + hl);
    int s1 = __ldg(bin + hl + 8);
    int s2 = __ldg(bin + hl + 16);
    int s3 = __ldg(bin + hl + 24);
    float acc = 0.0f;
    if (hl < len)      acc += __ldg(&g_gs[s0]);
    if (hl + 8 < len)  acc += __ldg(&g_gs[s1]);
    if (hl + 16 < len) acc += __ldg(&g_gs[s2]);
    if (hl + 24 < len) acc += __ldg(&g_gs[s3]);
    if (len > 32) {
        int s4 = __ldg(bin + hl + 32);
        int s5 = __ldg(bin + hl + 40);
        int s6 = __ldg(bin + hl + 48);
        int s7 = __ldg(bin + hl + 56);
        if (hl + 32 < len) acc += __ldg(&g_gs[s4]);
        if (hl + 40 < len) acc += __ldg(&g_gs[s5]);
        if (hl + 48 < len) acc += __ldg(&g_gs[s6]);
        if (hl + 56 < len) acc += __ldg(&g_gs[s7]);
    }
    if (hl == 0) {
        acc += __ldg(&g_gs[node]);   // self loop
        if (cnt > CAP) {             // overflow path (correct; ~never taken)
            int no = min(g_dyn.ovf_cnt, OVF_MAX);
            for (int o = 0; o < no; o++) {
                int2 rc = g_dyn.ovf[o];
                if (rc.y == node) acc += __ldg(&g_gs[rc.x]);
            }
        }
    }

    // reduce within the 8-lane group
    acc += __shfl_xor_sync(0xffffffffu, acc, 4);
    acc += __shfl_xor_sync(0xffffffffu, acc, 2);
    acc += __shfl_xor_sync(0xffffffffu, acc, 1);
    if (hl == 0) {
        float v = fmaf(acc, __ldg(&g_dinv[node]), __ldg(&b2[0]));
        out[node] = 1.0f / (1.0f + __expf(-v));
    }
}

// ---------------- launch ----------------------------------------------------
extern "C" void kernel_launch(void* const* d_in, const int* in_sizes, int n_in,
                              void* d_out, int out_size) {
    const float* x  = (const float*)d_in[0];
    const void*  ei = d_in[1];
    const float* W1 = (const float*)d_in[2];
    const float* b1 = (const float*)d_in[3];
    const float* W2 = (const float*)d_in[4];
    const float* b2 = (const float*)d_in[5];
    float* out = (float*)d_out;

    static void* dyn_addr = nullptr;
    if (!dyn_addr) cudaGetSymbolAddress(&dyn_addr, g_dyn);

    // zero cursors + ovf_cnt only (prefix of g_dyn)
    cudaMemsetAsync(dyn_addr, 0, (size_t)(NN + 1) * sizeof(int));
    k_fill_gemm<<<GEMM_BLKS + FILL_BLKS, 256>>>(x, W1, ei);
    k_scale<<<(NN + 255) / 256, 256>>>();
    k_gather1<<<(NN * 32 + 255) / 256, 256>>>(b1, W2);
    k_gather2<<<(NN * 8 + 255) / 256, 256>>>(b2, out);
}

// round 16
// speedup vs baseline: 1.0491x; 1.0181x over previous
#include <cuda_runtime.h>
#include <cuda_fp16.h>

#define NN 100000
#define NE 3200000
#define F1 16
#define CAP 64                       // slots per node (Poisson(32): P(>64)~4e-6/node; spill path handles rest)
#define OVF_MAX (1 << 20)

#define GEMM_BLKS 196                // 196 * 512 nodes
#define FILL_BLKS (NE / 4 / 256)     // 3125 (4 edges per thread)

// ---- static device scratch (no cudaMalloc allowed; zero-initialized at load)
__device__ float  g_h0f[NN * F1];    // (x @ W1) [* dinv after k_scale], fp32
__device__ float  g_gs[NN];          // layer-1 output * dinv[node]
__device__ float2 g_meta[NN];        // {dinv[node], count bits}
__device__ int    g_csr[NN * CAP];   // padded bins: src, grouped by dst
__device__ int    g_ovf_ro;          // snapshot of ovf_cnt for the gathers
__device__ struct {
    int cursor[NN];                  // reset to 0 by k_scale every launch
    int ovf_cnt;                     // reset to 0 by k_scale every launch
    int2 ovf[OVF_MAX];               // only first ovf_cnt entries valid
} g_dyn;

// ---- f32x2 helpers (Blackwell packed fp32) ----
__device__ __forceinline__ unsigned long long pack64(unsigned a, unsigned b) {
    unsigned long long r;
    asm("mov.b64 %0, {%1,%2};" : "=l"(r) : "r"(a), "r"(b));
    return r;
}
__device__ __forceinline__ void unpack64(unsigned long long v, float& a, float& b) {
    unsigned x, y;
    asm("mov.b64 {%0,%1}, %2;" : "=r"(x), "=r"(y) : "l"(v));
    a = __uint_as_float(x);
    b = __uint_as_float(y);
}
__device__ __forceinline__ void addx2(unsigned long long& acc, unsigned long long v) {
    asm("add.rn.f32x2 %0, %0, %1;" : "+l"(acc) : "l"(v));
}
__device__ __forceinline__ unsigned long long shfl_xor64(unsigned long long v, int off) {
    unsigned x, y;
    asm("mov.b64 {%0,%1}, %2;" : "=r"(x), "=r"(y) : "l"(v));
    x = __shfl_xor_sync(0xffffffffu, x, off);
    y = __shfl_xor_sync(0xffffffffu, y, off);
    return pack64(x, y);
}

// ---------------- fused: GEMM1 + CSR bin-fill (independent work) -----------
__global__ __launch_bounds__(256) void k_fill_gemm(
    const float* __restrict__ x, const float* __restrict__ W1,
    const void* __restrict__ ei) {
    if (blockIdx.x >= GEMM_BLKS) {
        // ---- inline dtype detect (parallel, L2-hot) ----
        int bad = 0;
        if (threadIdx.x < 64)
            bad = (__ldg((const unsigned int*)ei + 2 * threadIdx.x + 1) != 0u);
        int is64 = !__syncthreads_or(bad);

        // ---- fill: 4 edges/thread ----
        int base = ((blockIdx.x - GEMM_BLKS) * 256 + threadIdx.x) * 4;
        int r[4], c[4];
        if (is64) {
            const int4* p = (const int4*)ei;            // row half
            const int4* q = (const int4*)ei + NE / 2;   // col half
            int4 a = __ldg(p + base / 2);
            int4 b = __ldg(p + base / 2 + 1);
            int4 d = __ldg(q + base / 2);
            int4 e = __ldg(q + base / 2 + 1);
            r[0] = a.x; r[1] = a.z; r[2] = b.x; r[3] = b.z;
            c[0] = d.x; c[1] = d.z; c[2] = e.x; c[3] = e.z;
        } else {
            int4 a = __ldg((const int4*)((const int*)ei) + base / 4);
            int4 d = __ldg((const int4*)((const int*)ei + NE) + base / 4);
            r[0] = a.x; r[1] = a.y; r[2] = a.z; r[3] = a.w;
            c[0] = d.x; c[1] = d.y; c[2] = d.z; c[3] = d.w;
        }
        int s[4];
        #pragma unroll
        for (int j = 0; j < 4; j++) s[j] = atomicAdd(&g_dyn.cursor[c[j]], 1);
        #pragma unroll
        for (int j = 0; j < 4; j++) {
            if (s[j] < CAP) {
                g_csr[(c[j] << 6) + s[j]] = r[j];
            } else {                      // guaranteed-correct spill path
                int o = atomicAdd(&g_dyn.ovf_cnt, 1);
                if (o < OVF_MAX) g_dyn.ovf[o] = make_int2(r[j], c[j]);
            }
        }
        return;
    }
    // ---- GEMM: h0f = x @ W1, fp32, unscaled ----
    __shared__ float ws[128 * F1];
    for (int t = threadIdx.x; t < 128 * F1; t += 256) ws[t] = W1[t];
    __syncthreads();

    int nbase = blockIdx.x * 512 + threadIdx.x;
    float acc[2][F1];
    #pragma unroll
    for (int nn = 0; nn < 2; nn++)
        #pragma unroll
        for (int j = 0; j < F1; j++) acc[nn][j] = 0.0f;

    #pragma unroll 4
    for (int k4 = 0; k4 < 32; k4++) {
        float4 xr[2];
        #pragma unroll
        for (int nn = 0; nn < 2; nn++) {
            int node = nbase + nn * 256;
            xr[nn] = (node < NN)
                ? __ldg((const float4*)(x + (long long)node * 128) + k4)
                : make_float4(0.f, 0.f, 0.f, 0.f);
        }
        #pragma unroll
        for (int kk = 0; kk < 4; kk++) {
            #pragma unroll
            for (int j = 0; j < F1; j++) {
                float wv = ws[(k4 * 4 + kk) * F1 + j];
                #pragma unroll
                for (int nn = 0; nn < 2; nn++) {
                    const float* xa = (const float*)&xr[nn];
                    acc[nn][j] = fmaf(xa[kk], wv, acc[nn][j]);
                }
            }
        }
    }
    #pragma unroll
    for (int nn = 0; nn < 2; nn++) {
        int node = nbase + nn * 256;
        if (node < NN) {
            float4* o = (float4*)(g_h0f + (long long)node * F1);
            o[0] = make_float4(acc[nn][0], acc[nn][1], acc[nn][2], acc[nn][3]);
            o[1] = make_float4(acc[nn][4], acc[nn][5], acc[nn][6], acc[nn][7]);
            o[2] = make_float4(acc[nn][8], acc[nn][9], acc[nn][10], acc[nn][11]);
            o[3] = make_float4(acc[nn][12], acc[nn][13], acc[nn][14], acc[nn][15]);
        }
    }
}

// -------- scale: meta = {dinv, cnt}; h0f *= dinv; self-reset cursors -------
__global__ __launch_bounds__(256) void k_scale() {
    int i = blockIdx.x * 256 + threadIdx.x;
    if (i >= NN) return;
    int cnt = g_dyn.cursor[i];
    g_dyn.cursor[i] = 0;                        // self-reset for next replay
    if (i == 0) {
        g_ovf_ro = min(g_dyn.ovf_cnt, OVF_MAX); // snapshot for the gathers
        g_dyn.ovf_cnt = 0;                      // self-reset for next replay
    }
    float di = rsqrtf((float)cnt + 1.0f);
    g_meta[i] = make_float2(di, __int_as_float(cnt));
    float4* row = (float4*)(g_h0f + (long long)i * F1);
    #pragma unroll
    for (int j = 0; j < 4; j++) {
        float4 v = row[j];
        row[j] = make_float4(v.x * di, v.y * di, v.z * di, v.w * di);
    }
}

// ---------------- gather1: warp/node, 8-edge loop, f32x2 accumulate --------
// q = lane>>2 selects edge slot (8 per iter), f4 = lane&3 selects 16B quarter
__global__ __launch_bounds__(256) void k_gather1(
    const float* __restrict__ b1, const float* __restrict__ W2) {
    int node = (blockIdx.x * blockDim.x + threadIdx.x) >> 5;
    int lane = threadIdx.x & 31;
    if (node >= NN) return;
    float2 meta = __ldg(&g_meta[node]);
    float di = meta.x;
    int cnt = __float_as_int(meta.y);
    int len = min(cnt, CAP);
    const int* bin = g_csr + (node << 6);
    int q  = lane >> 2;
    int f4 = lane & 3;

    // packed accumulators: a01 = features (0,1) of the quarter, a23 = (2,3)
    unsigned long long a01 = 0ull, a23 = 0ull;
    if (q == 0) {
        uint4 s = __ldg((const uint4*)(g_h0f + (long long)node * F1) + f4);
        a01 = pack64(s.x, s.y);
        a23 = pack64(s.z, s.w);
    }

    for (int p = 0; p < len; p += 8) {
        int idx = p + q;
        if (idx < len) {
            int src = __ldg(bin + idx);
            uint4 v = __ldg((const uint4*)(g_h0f + (long long)src * F1) + f4);
            addx2(a01, pack64(v.x, v.y));
            addx2(a23, pack64(v.z, v.w));
        }
    }
    // reduce across the 8 edge-slots (keep f4 split): packed adds
    #pragma unroll
    for (int off = 4; off < 32; off <<= 1) {
        addx2(a01, shfl_xor64(a01, off));
        addx2(a23, shfl_xor64(a23, off));
    }
    float v = 0.0f;
    if (lane < 4) {
        float ax, ay, az, aw;
        unpack64(a01, ax, ay);
        unpack64(a23, az, aw);
        if (cnt > CAP) {    // overflow path (correct; ~never taken)
            int no = g_ovf_ro;
            for (int o = 0; o < no; o++) {
                int2 rc = g_dyn.ovf[o];
                if (rc.y == node) {
                    float4 u = __ldg((const float4*)(g_h0f + (long long)rc.x * F1) + f4);
                    ax += u.x; ay += u.y; az += u.z; aw += u.w;
                }
            }
        }
        float4 bb = __ldg((const float4*)b1 + lane);
        float4 ww = __ldg((const float4*)W2 + lane);
        float t0 = fmaxf(fmaf(ax, di, bb.x), 0.f) * ww.x;
        float t1 = fmaxf(fmaf(ay, di, bb.y), 0.f) * ww.y;
        float t2 = fmaxf(fmaf(az, di, bb.z), 0.f) * ww.z;
        float t3 = fmaxf(fmaf(aw, di, bb.w), 0.f) * ww.w;
        v = (t0 + t1) + (t2 + t3);
    }
    v += __shfl_xor_sync(0xffffffffu, v, 1);
    v += __shfl_xor_sync(0xffffffffu, v, 2);
    if (lane == 0) g_gs[node] = v * di;
}

// ---------------- gather2: 4 nodes/warp, 8 lanes/node -----------------------
__global__ __launch_bounds__(256) void k_gather2(
    const float* __restrict__ b2, float* __restrict__ out) {
    int w = (blockIdx.x * blockDim.x + threadIdx.x) >> 5;
    int lane = threadIdx.x & 31;
    int sub = lane >> 3;             // which node in this warp (0..3)
    int hl  = lane & 7;              // lane within 8-lane group
    int node = w * 4 + sub;
    if (node >= NN) return;
    float2 meta = __ldg(&g_meta[node]);
    int cnt = __float_as_int(meta.y);
    int len = min(cnt, CAP);
    const int* bin = g_csr + (node << 6);

    // 4 (or 8) independent csr+gather chains per lane
    int s0 = __ldg(bin + hl);
    int s1 = __ldg(bin + hl + 8);
    int s2 = __ldg(bin + hl + 16);
    int s3 = __ldg(bin + hl + 24);
    float acc = 0.0f;
    if (hl < len)      acc += __ldg(&g_gs[s0]);
    if (hl + 8 < len)  acc += __ldg(&g_gs[s1]);
    if (hl + 16 < len) acc += __ldg(&g_gs[s2]);
    if (hl + 24 < len) acc += __ldg(&g_gs[s3]);
    if (len > 32) {
        int s4 = __ldg(bin + hl + 32);
        int s5 = __ldg(bin + hl + 40);
        int s6 = __ldg(bin + hl + 48);
        int s7 = __ldg(bin + hl + 56);
        if (hl + 32 < len) acc += __ldg(&g_gs[s4]);
        if (hl + 40 < len) acc += __ldg(&g_gs[s5]);
        if (hl + 48 < len) acc += __ldg(&g_gs[s6]);
        if (hl + 56 < len) acc += __ldg(&g_gs[s7]);
    }
    if (hl == 0) {
        acc += __ldg(&g_gs[node]);   // self loop
        if (cnt > CAP) {             // overflow path (correct; ~never taken)
            int no = g_ovf_ro;
            for (int o = 0; o < no; o++) {
                int2 rc = g_dyn.ovf[o];
                if (rc.y == node) acc += __ldg(&g_gs[rc.x]);
            }
        }
    }

    // reduce within the 8-lane group
    acc += __shfl_xor_sync(0xffffffffu, acc, 4);
    acc += __shfl_xor_sync(0xffffffffu, acc, 2);
    acc += __shfl_xor_sync(0xffffffffu, acc, 1);
    if (hl == 0) {
        float v = fmaf(acc, meta.x, __ldg(&b2[0]));
        out[node] = 1.0f / (1.0f + __expf(-v));
    }
}

// ---------------- launch ----------------------------------------------------
extern "C" void kernel_launch(void* const* d_in, const int* in_sizes, int n_in,
                              void* d_out, int out_size) {
    const float* x  = (const float*)d_in[0];
    const void*  ei = d_in[1];
    const float* W1 = (const float*)d_in[2];
    const float* b1 = (const float*)d_in[3];
    const float* W2 = (const float*)d_in[4];
    const float* b2 = (const float*)d_in[5];
    float* out = (float*)d_out;

    // no memset: cursors/ovf_cnt are zero at load and self-reset by k_scale
    k_fill_gemm<<<GEMM_BLKS + FILL_BLKS, 256>>>(x, W1, ei);
    k_scale<<<(NN + 255) / 256, 256>>>();
    k_gather1<<<(NN * 32 + 255) / 256, 256>>>(b1, W2);
    k_gather2<<<(NN * 8 + 255) / 256, 256>>>(b2, out);
}

// round 17
// speedup vs baseline: 1.0988x; 1.0473x over previous
#include <cuda_runtime.h>
#include <cuda_fp16.h>

#define NN 100000
#define NE 3200000
#define F1 16
#define CAP 64                       // slots per node (Poisson(32): P(>64)~4e-6/node; spill path handles rest)
#define OVF_MAX (1 << 20)

#define GEMM_BLKS 196                // 196 * 512 nodes
#define FILL_BLKS (NE / 4 / 256)     // 3125 (4 edges per thread)

// ---- static device scratch (no cudaMalloc allowed; zero-initialized at load)
__device__ float  g_h0f[NN * F1];    // (x @ W1) [* dinv after k_scale], fp32
__device__ float  g_gs[NN];          // layer-1 output * dinv[node]
__device__ float2 g_meta[NN];        // {dinv[node], count bits}
__device__ int    g_csr[NN * CAP];   // padded bins: src, grouped by dst
__device__ int    g_ovf_ro;          // snapshot of ovf_cnt for the gathers
__device__ struct {
    int cursor[NN];                  // reset to 0 by k_scale every launch
    int ovf_cnt;                     // reset to 0 by k_scale every launch
    int2 ovf[OVF_MAX];               // only first ovf_cnt entries valid
} g_dyn;

// ---- f32x2 helpers (Blackwell packed fp32) ----
__device__ __forceinline__ unsigned long long pack64(unsigned a, unsigned b) {
    unsigned long long r;
    asm("mov.b64 %0, {%1,%2};" : "=l"(r) : "r"(a), "r"(b));
    return r;
}
__device__ __forceinline__ void unpack64(unsigned long long v, float& a, float& b) {
    unsigned x, y;
    asm("mov.b64 {%0,%1}, %2;" : "=r"(x), "=r"(y) : "l"(v));
    a = __uint_as_float(x);
    b = __uint_as_float(y);
}
__device__ __forceinline__ void addx2(unsigned long long& acc, unsigned long long v) {
    asm("add.rn.f32x2 %0, %0, %1;" : "+l"(acc) : "l"(v));
}
__device__ __forceinline__ unsigned long long shfl_xor64(unsigned long long v, int off) {
    unsigned x, y;
    asm("mov.b64 {%0,%1}, %2;" : "=r"(x), "=r"(y) : "l"(v));
    x = __shfl_xor_sync(0xffffffffu, x, off);
    y = __shfl_xor_sync(0xffffffffu, y, off);
    return pack64(x, y);
}

// ---------------- fused: GEMM1 + CSR bin-fill (independent work) -----------
__global__ __launch_bounds__(256) void k_fill_gemm(
    const float* __restrict__ x, const float* __restrict__ W1,
    const void* __restrict__ ei) {
    if (blockIdx.x >= GEMM_BLKS) {
        // ---- inline dtype detect (parallel, L2-hot) ----
        int bad = 0;
        if (threadIdx.x < 64)
            bad = (__ldg((const unsigned int*)ei + 2 * threadIdx.x + 1) != 0u);
        int is64 = !__syncthreads_or(bad);

        // ---- fill: 4 edges/thread ----
        int base = ((blockIdx.x - GEMM_BLKS) * 256 + threadIdx.x) * 4;
        int r[4], c[4];
        if (is64) {
            const int4* p = (const int4*)ei;            // row half
            const int4* q = (const int4*)ei + NE / 2;   // col half
            int4 a = __ldg(p + base / 2);
            int4 b = __ldg(p + base / 2 + 1);
            int4 d = __ldg(q + base / 2);
            int4 e = __ldg(q + base / 2 + 1);
            r[0] = a.x; r[1] = a.z; r[2] = b.x; r[3] = b.z;
            c[0] = d.x; c[1] = d.z; c[2] = e.x; c[3] = e.z;
        } else {
            int4 a = __ldg((const int4*)((const int*)ei) + base / 4);
            int4 d = __ldg((const int4*)((const int*)ei + NE) + base / 4);
            r[0] = a.x; r[1] = a.y; r[2] = a.z; r[3] = a.w;
            c[0] = d.x; c[1] = d.y; c[2] = d.z; c[3] = d.w;
        }
        int s[4];
        #pragma unroll
        for (int j = 0; j < 4; j++) s[j] = atomicAdd(&g_dyn.cursor[c[j]], 1);
        #pragma unroll
        for (int j = 0; j < 4; j++) {
            if (s[j] < CAP) {
                g_csr[(c[j] << 6) + s[j]] = r[j];
            } else {                      // guaranteed-correct spill path
                int o = atomicAdd(&g_dyn.ovf_cnt, 1);
                if (o < OVF_MAX) g_dyn.ovf[o] = make_int2(r[j], c[j]);
            }
        }
        return;
    }
    // ---- GEMM: h0f = x @ W1, fp32, unscaled ----
    __shared__ float ws[128 * F1];
    for (int t = threadIdx.x; t < 128 * F1; t += 256) ws[t] = W1[t];
    __syncthreads();

    int nbase = blockIdx.x * 512 + threadIdx.x;
    float acc[2][F1];
    #pragma unroll
    for (int nn = 0; nn < 2; nn++)
        #pragma unroll
        for (int j = 0; j < F1; j++) acc[nn][j] = 0.0f;

    #pragma unroll 4
    for (int k4 = 0; k4 < 32; k4++) {
        float4 xr[2];
        #pragma unroll
        for (int nn = 0; nn < 2; nn++) {
            int node = nbase + nn * 256;
            xr[nn] = (node < NN)
                ? __ldg((const float4*)(x + (long long)node * 128) + k4)
                : make_float4(0.f, 0.f, 0.f, 0.f);
        }
        #pragma unroll
        for (int kk = 0; kk < 4; kk++) {
            #pragma unroll
            for (int j = 0; j < F1; j++) {
                float wv = ws[(k4 * 4 + kk) * F1 + j];
                #pragma unroll
                for (int nn = 0; nn < 2; nn++) {
                    const float* xa = (const float*)&xr[nn];
                    acc[nn][j] = fmaf(xa[kk], wv, acc[nn][j]);
                }
            }
        }
    }
    #pragma unroll
    for (int nn = 0; nn < 2; nn++) {
        int node = nbase + nn * 256;
        if (node < NN) {
            float4* o = (float4*)(g_h0f + (long long)node * F1);
            o[0] = make_float4(acc[nn][0], acc[nn][1], acc[nn][2], acc[nn][3]);
            o[1] = make_float4(acc[nn][4], acc[nn][5], acc[nn][6], acc[nn][7]);
            o[2] = make_float4(acc[nn][8], acc[nn][9], acc[nn][10], acc[nn][11]);
            o[3] = make_float4(acc[nn][12], acc[nn][13], acc[nn][14], acc[nn][15]);
        }
    }
}

// -------- scale: meta = {dinv, cnt}; h0f *= dinv; self-reset cursors -------
__global__ __launch_bounds__(256) void k_scale() {
    int i = blockIdx.x * 256 + threadIdx.x;
    if (i >= NN) return;
    int cnt = g_dyn.cursor[i];
    g_dyn.cursor[i] = 0;                        // self-reset for next replay
    if (i == 0) {
        g_ovf_ro = min(g_dyn.ovf_cnt, OVF_MAX); // snapshot for the gathers
        g_dyn.ovf_cnt = 0;                      // self-reset for next replay
    }
    float di = rsqrtf((float)cnt + 1.0f);
    g_meta[i] = make_float2(di, __int_as_float(cnt));
    float4* row = (float4*)(g_h0f + (long long)i * F1);
    #pragma unroll
    for (int j = 0; j < 4; j++) {
        float4 v = row[j];
        row[j] = make_float4(v.x * di, v.y * di, v.z * di, v.w * di);
    }
}

// ------- gather1: 2 nodes/warp, 16 lanes/node, 4-edge loop, f32x2 ----------
// hlane = lane&15; q = hlane>>2 selects edge slot, f4 = hlane&3 = 16B quarter
__global__ __launch_bounds__(256) void k_gather1(
    const float* __restrict__ b1, const float* __restrict__ W2) {
    int w = (blockIdx.x * blockDim.x + threadIdx.x) >> 5;
    int lane = threadIdx.x & 31;
    int node = w * 2 + (lane >> 4);
    if (node >= NN) return;
    int hlane = lane & 15;
    float2 meta = __ldg(&g_meta[node]);
    float di = meta.x;
    int cnt = __float_as_int(meta.y);
    int len = min(cnt, CAP);
    const int* bin = g_csr + (node << 6);
    int q  = hlane >> 2;
    int f4 = hlane & 3;

    // packed accumulators: a01 = features (0,1) of the quarter, a23 = (2,3)
    unsigned long long a01 = 0ull, a23 = 0ull;
    if (q == 0) {   // self-loop (h0f already dinv-scaled)
        uint4 s = __ldg((const uint4*)(g_h0f + (long long)node * F1) + f4);
        a01 = pack64(s.x, s.y);
        a23 = pack64(s.z, s.w);
    }

    for (int p = 0; p < len; p += 4) {
        int idx = p + q;
        if (idx < len) {
            int src = __ldg(bin + idx);
            uint4 v = __ldg((const uint4*)(g_h0f + (long long)src * F1) + f4);
            addx2(a01, pack64(v.x, v.y));
            addx2(a23, pack64(v.z, v.w));
        }
    }
    // reduce across the 4 edge-slot groups within the 16-lane half
    addx2(a01, shfl_xor64(a01, 4));
    addx2(a23, shfl_xor64(a23, 4));
    addx2(a01, shfl_xor64(a01, 8));
    addx2(a23, shfl_xor64(a23, 8));

    float v = 0.0f;
    if (hlane < 4) {
        float ax, ay, az, aw;
        unpack64(a01, ax, ay);
        unpack64(a23, az, aw);
        if (cnt > CAP) {    // overflow path (correct; ~never taken)
            int no = g_ovf_ro;
            for (int o = 0; o < no; o++) {
                int2 rc = g_dyn.ovf[o];
                if (rc.y == node) {
                    float4 u = __ldg((const float4*)(g_h0f + (long long)rc.x * F1) + f4);
                    ax += u.x; ay += u.y; az += u.z; aw += u.w;
                }
            }
        }
        float4 bb = __ldg((const float4*)b1 + hlane);
        float4 ww = __ldg((const float4*)W2 + hlane);
        float t0 = fmaxf(fmaf(ax, di, bb.x), 0.f) * ww.x;
        float t1 = fmaxf(fmaf(ay, di, bb.y), 0.f) * ww.y;
        float t2 = fmaxf(fmaf(az, di, bb.z), 0.f) * ww.z;
        float t3 = fmaxf(fmaf(aw, di, bb.w), 0.f) * ww.w;
        v = (t0 + t1) + (t2 + t3);
    }
    v += __shfl_xor_sync(0xffffffffu, v, 1);
    v += __shfl_xor_sync(0xffffffffu, v, 2);
    if (hlane == 0) g_gs[node] = v * di;
}

// ------------- gather2: 4 nodes/warp, 8 lanes/node, int4 csr ----------------
__global__ __launch_bounds__(256) void k_gather2(
    const float* __restrict__ b2, float* __restrict__ out) {
    int w = (blockIdx.x * blockDim.x + threadIdx.x) >> 5;
    int lane = threadIdx.x & 31;
    int sub = lane >> 3;             // which node in this warp (0..3)
    int hl  = lane & 7;              // lane within 8-lane group
    int node = w * 4 + sub;
    if (node >= NN) return;
    float2 meta = __ldg(&g_meta[node]);
    int cnt = __float_as_int(meta.y);
    int len = min(cnt, CAP);
    const int4* bin4 = (const int4*)(g_csr + (node << 6));

    // lane hl owns slots [4hl, 4hl+4): one int4 csr load, 4 independent gathers
    int4 s = __ldg(bin4 + hl);
    int b0 = hl * 4;
    float acc = 0.0f;
    if (b0 < len)     acc += __ldg(&g_gs[s.x]);
    if (b0 + 1 < len) acc += __ldg(&g_gs[s.y]);
    if (b0 + 2 < len) acc += __ldg(&g_gs[s.z]);
    if (b0 + 3 < len) acc += __ldg(&g_gs[s.w]);
    if (len > 32) {
        int4 s2 = __ldg(bin4 + 8 + hl);
        int b1_ = 32 + hl * 4;
        if (b1_ < len)     acc += __ldg(&g_gs[s2.x]);
        if (b1_ + 1 < len) acc += __ldg(&g_gs[s2.y]);
        if (b1_ + 2 < len) acc += __ldg(&g_gs[s2.z]);
        if (b1_ + 3 < len) acc += __ldg(&g_gs[s2.w]);
    }
    if (hl == 0) {
        acc += __ldg(&g_gs[node]);   // self loop
        if (cnt > CAP) {             // overflow path (correct; ~never taken)
            int no = g_ovf_ro;
            for (int o = 0; o < no; o++) {
                int2 rc = g_dyn.ovf[o];
                if (rc.y == node) acc += __ldg(&g_gs[rc.x]);
            }
        }
    }

    // reduce within the 8-lane group
    acc += __shfl_xor_sync(0xffffffffu, acc, 4);
    acc += __shfl_xor_sync(0xffffffffu, acc, 2);
    acc += __shfl_xor_sync(0xffffffffu, acc, 1);
    if (hl == 0) {
        float v = fmaf(acc, meta.x, __ldg(&b2[0]));
        out[node] = 1.0f / (1.0f + __expf(-v));
    }
}

// ---------------- launch ----------------------------------------------------
extern "C" void kernel_launch(void* const* d_in, const int* in_sizes, int n_in,
                              void* d_out, int out_size) {
    const float* x  = (const float*)d_in[0];
    const void*  ei = d_in[1];
    const float* W1 = (const float*)d_in[2];
    const float* b1 = (const float*)d_in[3];
    const float* W2 = (const float*)d_in[4];
    const float* b2 = (const float*)d_in[5];
    float* out = (float*)d_out;

    // no memset: cursors/ovf_cnt are zero at load and self-reset by k_scale
    k_fill_gemm<<<GEMM_BLKS + FILL_BLKS, 256>>>(x, W1, ei);
    k_scale<<<(NN + 255) / 256, 256>>>();
    k_gather1<<<(NN * 16 + 255) / 256, 256>>>(b1, W2);
    k_gather2<<<(NN * 8 + 255) / 256, 256>>>(b2, out);
}